// round 13
// baseline (speedup 1.0000x reference)
#include <cuda_runtime.h>
#include <cuda_fp16.h>
#include <mma.h>
#include <cstdint>

using namespace nvcuda;

#define N_NODES 100000
#define N_EDGES 1600000
#define IN_CH   512
#define HID     128
#define OUT_CH  64
#define SCAN_BLK ((N_NODES + 255) / 256)   // 391
#define M_TILES  ((N_NODES + 127) / 128)   // 782
#define M_PAD    (M_TILES * 128)           // 100096
#define SPLIT    (391 * 128)               // 50048: tile-aligned row split

#define LDAH 40          // A stage: 32 + 8 pad (halfs)

// ---------------- scratch (device globals; no allocation allowed) ----------
__device__ __half g_h0[(size_t)M_PAD * HID];
__device__ __half g_h1[(size_t)M_PAD * HID];
__device__ __half g_W1h[IN_CH * HID];
__device__ __half g_Wch[HID * HID];
__device__ __half g_W2h[HID * OUT_CH];
__device__ float  g_dinv[N_NODES];
__device__ int    g_count[N_NODES];
__device__ int    g_fill[N_NODES];
__device__ int    g_rowptr[N_NODES + 1];
__device__ int    g_col[N_EDGES];
__device__ float  g_val[N_EDGES];
__device__ int    g_part[SCAN_BLK];
__device__ int    g_pscan[SCAN_BLK];
__device__ int    g_is64;

// ---------------- helpers --------------------------------------------------
__device__ __forceinline__ float gelu_exact(float v) {
    return 0.5f * v * (1.0f + erff(v * 0.7071067811865476f));
}

__device__ __forceinline__ int clampN(int v) {
    return min(max(v, 0), N_NODES - 1);
}

__device__ __forceinline__ int edge_at(const void* ei, int k) {
    if (g_is64) return (int)((const long long*)ei)[k];
    return ((const int*)ei)[k];
}

__device__ __forceinline__ void cp_async16(void* smem, const void* g) {
    uint32_t s = (uint32_t)__cvta_generic_to_shared(smem);
    asm volatile("cp.async.cg.shared.global [%0], [%1], 16;"
                 :: "r"(s), "l"(g));
}

__device__ __forceinline__ uint2 f4_to_h4(float4 v) {
    __half2 a = __floats2half2_rn(v.x, v.y);
    __half2 b = __floats2half2_rn(v.z, v.w);
    uint2 u;
    u.x = *reinterpret_cast<uint32_t*>(&a);
    u.y = *reinterpret_cast<uint32_t*>(&b);
    return u;
}

__device__ __forceinline__ float4 row_load4(const __half* X, int row, int lane) {
    uint2 u = __ldg(((const uint2*)(X + (size_t)row * HID)) + lane);
    __half2 a = *reinterpret_cast<__half2*>(&u.x);
    __half2 b = *reinterpret_cast<__half2*>(&u.y);
    float2 f0 = __half22float2(a);
    float2 f1 = __half22float2(b);
    return make_float4(f0.x, f0.y, f1.x, f1.y);
}
__device__ __forceinline__ void row_store4(float* Y, int row, int lane, float4 v) {
    ((float4*)(Y + (size_t)row * HID))[lane] = v;
}
__device__ __forceinline__ void row_store4(__half* Y, int row, int lane, float4 v) {
    ((uint2*)(Y + (size_t)row * HID))[lane] = f4_to_h4(v);
}

// ---------------- fp16 HMMA GEMM, 2-stage double buffer ---------------------
// BM=128, BK=32, 8 warps, 2 CTAs/SM. Row range [rowStart, Mlim).
// AT=float : A loaded via LDG, converted to fp16, STS (register staging).
// AT=half  : A loaded via cp.async (already fp16).
// MODE 1: fused bias + exact-GELU + LayerNorm epilogue -> OutT.
// MODE 2: staged bias-only epilogue (fp32, guarded) for d_out.
template <int BN, int MODE, typename AT, typename OutT>
__global__ void __launch_bounds__(256, 2)
hgemm_kernel(const AT* __restrict__ A,
             const __half* __restrict__ Bm,
             const float* __restrict__ bias,
             const float* __restrict__ gamma,
             const float* __restrict__ beta,
             OutT* __restrict__ C,
             int rowStart, int Mlim, int K) {
    constexpr int BM = 128, BK = 32;
    constexpr int LDBH = BN + 8;
    constexpr int WN = (BN == 128) ? 4 : 2;
    constexpr int ASZ = BM * LDAH;        // halfs per A stage
    constexpr int BSZ = BK * LDBH;        // halfs per B stage
    constexpr bool A_F32 = (sizeof(AT) == 4);

    extern __shared__ __align__(16) char dsm[];
    __half* Ah = (__half*)dsm;            // [2][ASZ]
    __half* Bh = Ah + 2 * ASZ;            // [2][BSZ]
    float*  Cs = (float*)dsm;             // reused after mainloop

    const int tid   = threadIdx.x;
    const int wid   = tid >> 5;
    const int lane  = tid & 31;
    const int warpM = wid & 3;
    const int warpN = wid >> 2;
    const int rowBase = rowStart + blockIdx.x * BM;
    const int kIters = K / BK;

    // B tile via cp.async: BK rows x BN halfs
    auto loadB = [&](int k0, int buf) {
        constexpr int CH = BK * BN / 8;   // 16B chunks: 512 (BN=128) / 256
#pragma unroll
        for (int i = 0; i < (CH + 255) / 256; i++) {
            int lin = tid + i * 256;
            if (CH < 256 || lin < CH) {
                int r = lin / (BN / 8);
                int c8 = (lin % (BN / 8)) * 8;
                cp_async16(&Bh[buf * BSZ + r * LDBH + c8],
                           Bm + (size_t)(k0 + r) * BN + c8);
            }
        }
    };

    // A tile, fp32 source: 4 float4 per thread (128x32 fp32)
    float4 aregs[4];
    auto loadA_f32 = [&](int k0) {
#pragma unroll
        for (int i = 0; i < 4; i++) {
            int lin = tid + i * 256;
            int r = lin >> 3;
            int c4 = (lin & 7) * 4;
            int gr = min(rowBase + r, Mlim - 1);
            aregs[i] = *(const float4*)((const float*)A + (size_t)gr * K + k0 + c4);
        }
    };
    auto stsA_f32 = [&](int buf) {
#pragma unroll
        for (int i = 0; i < 4; i++) {
            int lin = tid + i * 256;
            int r = lin >> 3;
            int c4 = (lin & 7) * 4;
            *(uint2*)&Ah[buf * ASZ + r * LDAH + c4] = f4_to_h4(aregs[i]);
        }
    };

    // A tile, fp16 source via cp.async: 128x32 halfs = 512 chunks, 2/thread
    auto loadA_f16 = [&](int k0, int buf) {
#pragma unroll
        for (int i = 0; i < 2; i++) {
            int lin = tid + i * 256;
            int r = lin >> 2;
            int c8 = (lin & 3) * 8;
            int gr = min(rowBase + r, Mlim - 1);
            cp_async16(&Ah[buf * ASZ + r * LDAH + c8],
                       (const __half*)A + (size_t)gr * K + k0 + c8);
        }
    };

    wmma::fragment<wmma::accumulator, 16, 16, 16, float> acc[2][WN];
#pragma unroll
    for (int i = 0; i < 2; i++)
#pragma unroll
        for (int j = 0; j < WN; j++) wmma::fill_fragment(acc[i][j], 0.0f);

    // prologue
    if (A_F32) {
        loadA_f32(0);
        loadB(0, 0);
        asm volatile("cp.async.commit_group;");
        stsA_f32(0);
    } else {
        loadA_f16(0, 0);
        loadB(0, 0);
        asm volatile("cp.async.commit_group;");
    }
    asm volatile("cp.async.wait_group 0;");
    __syncthreads();

    for (int it = 0; it < kIters; it++) {
        const int cur = it & 1;
        const bool more = (it + 1 < kIters);
        if (more) {
            if (A_F32) {
                loadA_f32((it + 1) * BK);
                loadB((it + 1) * BK, cur ^ 1);
            } else {
                loadA_f16((it + 1) * BK, cur ^ 1);
                loadB((it + 1) * BK, cur ^ 1);
            }
            asm volatile("cp.async.commit_group;");
        }

        const __half* as = Ah + cur * ASZ;
        const __half* bs = Bh + cur * BSZ;
#pragma unroll
        for (int kk = 0; kk < BK; kk += 16) {
            wmma::fragment<wmma::matrix_a, 16, 16, 16, __half, wmma::row_major> af[2];
#pragma unroll
            for (int i = 0; i < 2; i++)
                wmma::load_matrix_sync(af[i], as + (warpM * 32 + i * 16) * LDAH + kk, LDAH);
#pragma unroll
            for (int j = 0; j < WN; j++) {
                wmma::fragment<wmma::matrix_b, 16, 16, 16, __half, wmma::row_major> bf;
                wmma::load_matrix_sync(bf, bs + kk * LDBH + warpN * WN * 16 + j * 16, LDBH);
                wmma::mma_sync(acc[0][j], af[0], bf, acc[0][j]);
                wmma::mma_sync(acc[1][j], af[1], bf, acc[1][j]);
            }
        }

        if (more) {
            if (A_F32) stsA_f32(cur ^ 1);
            asm volatile("cp.async.wait_group 0;");
            __syncthreads();
        }
    }

    __syncthreads();   // all warps done with tiles before smem reuse

    // ---- stage C tile to smem ----
#pragma unroll
    for (int i = 0; i < 2; i++)
#pragma unroll
        for (int j = 0; j < WN; j++) {
            int r = warpM * 32 + i * 16;
            int c = warpN * WN * 16 + j * 16;
            wmma::store_matrix_sync(Cs + (size_t)r * BN + c, acc[i][j], BN,
                                    wmma::mem_row_major);
        }
    __syncthreads();

    if (MODE == 1) {
        float4 bb = ((const float4*)bias)[lane];
        float4 gg = ((const float4*)gamma)[lane];
        float4 be = ((const float4*)beta)[lane];
#pragma unroll
        for (int i = 0; i < 16; i++) {
            int r = wid * 16 + i;
            int gr = rowBase + r;
            float4 v = ((const float4*)(Cs + (size_t)r * BN))[lane];
            v.x = gelu_exact(v.x + bb.x);
            v.y = gelu_exact(v.y + bb.y);
            v.z = gelu_exact(v.z + bb.z);
            v.w = gelu_exact(v.w + bb.w);
            float s  = v.x + v.y + v.z + v.w;
            float sq = v.x * v.x + v.y * v.y + v.z * v.z + v.w * v.w;
#pragma unroll
            for (int off = 16; off > 0; off >>= 1) {
                s  += __shfl_xor_sync(0xffffffffu, s, off);
                sq += __shfl_xor_sync(0xffffffffu, sq, off);
            }
            float mu   = s * (1.0f / HID);
            float var  = sq * (1.0f / HID) - mu * mu;
            float rstd = rsqrtf(var + 1e-5f);
            float4 o;
            o.x = (v.x - mu) * rstd * gg.x + be.x;
            o.y = (v.y - mu) * rstd * gg.y + be.y;
            o.z = (v.z - mu) * rstd * gg.z + be.z;
            o.w = (v.w - mu) * rstd * gg.w + be.w;
            if (gr < Mlim) row_store4(C, gr, lane, o);
        }
    } else {
        constexpr int C4 = BM * BN / 4;
#pragma unroll
        for (int i = 0; i < C4 / 256; i++) {
            int lin = tid + i * 256;
            int r = lin / (BN / 4);
            int c = (lin % (BN / 4)) * 4;
            int gr = rowBase + r;
            if (gr < Mlim) {
                float4 v = *(float4*)(Cs + (size_t)r * BN + c);
                v.x += bias[c + 0];
                v.y += bias[c + 1];
                v.z += bias[c + 2];
                v.w += bias[c + 3];
                *(float4*)((float*)C + (size_t)gr * BN + c) = v;
            }
        }
    }
}

// ---------------- weight conversion ----------------------------------------
__global__ void convert_w1_kernel(const float* __restrict__ W1) {
    int i = blockIdx.x * blockDim.x + threadIdx.x;
    if (i < IN_CH * HID) g_W1h[i] = __float2half_rn(W1[i]);
}

__global__ void convert_wc2_kernel(const float* __restrict__ Wc,
                                   const float* __restrict__ W2) {
    int i = blockIdx.x * blockDim.x + threadIdx.x;
    if (i < HID * HID)    g_Wch[i] = __float2half_rn(Wc[i]);
    if (i < HID * OUT_CH) g_W2h[i] = __float2half_rn(W2[i]);
}

// ---------------- CSR build (side stream, overlapped with GEMM1) -----------
__global__ void zero_probe_kernel(const int* __restrict__ a) {
    int i = blockIdx.x * blockDim.x + threadIdx.x;
    if (i < N_NODES) { g_count[i] = 0; g_fill[i] = 0; }
    if (blockIdx.x == 0 && threadIdx.x == 0) {
        int all0 = 1;
        for (int k = 1; k < 64; k += 2) all0 &= (a[k] == 0);
        g_is64 = all0;
    }
}

__global__ void count_kernel(const void* __restrict__ ei) {
    int e = blockIdx.x * blockDim.x + threadIdx.x;
    if (e >= N_EDGES) return;
    int d = clampN(edge_at(ei, N_EDGES + e));
    atomicAdd(&g_count[d], 1);
}

__global__ void part_dinv_kernel() {
    __shared__ int sdata[256];
    int tid = threadIdx.x;
    int idx = blockIdx.x * 256 + tid;
    int c = (idx < N_NODES) ? g_count[idx] : 0;
    if (idx < N_NODES) g_dinv[idx] = rsqrtf((float)(c + 1));  // +1 self-loop
    sdata[tid] = c;
    __syncthreads();
    for (int s = 128; s > 0; s >>= 1) {
        if (tid < s) sdata[tid] += sdata[tid + s];
        __syncthreads();
    }
    if (tid == 0) g_part[blockIdx.x] = sdata[0];
}

__global__ void pscan_kernel() {
    __shared__ int wsums[16];
    int tid = threadIdx.x;
    int lane = tid & 31;
    int wid = tid >> 5;
    int v = (tid < SCAN_BLK) ? g_part[tid] : 0;
    int incl = v;
#pragma unroll
    for (int off = 1; off < 32; off <<= 1) {
        int n = __shfl_up_sync(0xffffffffu, incl, off);
        if (lane >= off) incl += n;
    }
    if (lane == 31) wsums[wid] = incl;
    __syncthreads();
    if (tid == 0) {
        int s = 0;
#pragma unroll
        for (int i = 0; i < 16; i++) { int t = wsums[i]; wsums[i] = s; s += t; }
    }
    __syncthreads();
    if (tid < SCAN_BLK) g_pscan[tid] = incl - v + wsums[wid];
}

__global__ void rowptr_scan_kernel() {
    __shared__ int wsums[8];
    int tid = threadIdx.x;
    int lane = tid & 31;
    int wid = tid >> 5;
    int idx = blockIdx.x * 256 + tid;
    int v = (idx < N_NODES) ? g_count[idx] : 0;
    int incl = v;
#pragma unroll
    for (int off = 1; off < 32; off <<= 1) {
        int n = __shfl_up_sync(0xffffffffu, incl, off);
        if (lane >= off) incl += n;
    }
    if (lane == 31) wsums[wid] = incl;
    __syncthreads();
    if (tid == 0) {
        int s = 0;
#pragma unroll
        for (int i = 0; i < 8; i++) { int t = wsums[i]; wsums[i] = s; s += t; }
    }
    __syncthreads();
    int excl = incl - v + wsums[wid] + g_pscan[blockIdx.x];
    if (idx <= N_NODES) g_rowptr[idx] = excl;
}

__global__ void fill_kernel(const void* __restrict__ ei) {
    int e = blockIdx.x * blockDim.x + threadIdx.x;
    if (e >= N_EDGES) return;
    int s = clampN(edge_at(ei, e));
    int d = clampN(edge_at(ei, N_EDGES + e));
    int pos = g_rowptr[d] + atomicAdd(&g_fill[d], 1);
    pos = min(max(pos, 0), N_EDGES - 1);
    g_col[pos] = s;
    g_val[pos] = g_dinv[s] * g_dinv[d];
}

// ---------------- pull-mode SpMM hop (warp per dst row, row range) ----------
__global__ void spmm_hop_kernel(const __half* __restrict__ X,
                                __half* __restrict__ Y,
                                int rowStart, int rowEnd) {
    int row = rowStart + ((blockIdx.x * blockDim.x + threadIdx.x) >> 5);
    int lane = threadIdx.x & 31;
    if (row >= rowEnd) return;
    int start = g_rowptr[row];
    int end   = g_rowptr[row + 1];
    start = min(max(start, 0), N_EDGES);
    end   = min(max(end, start), N_EDGES);
    float di = g_dinv[row];
    float w0 = di * di;
    float4 v = row_load4(X, row, lane);
    float4 acc;
    acc.x = w0 * v.x; acc.y = w0 * v.y; acc.z = w0 * v.z; acc.w = w0 * v.w;

    for (int j = start; j < end; j += 32) {
        int idx = j + lane;
        int c = 0;
        float wv = 0.0f;
        if (idx < end) { c = clampN(g_col[idx]); wv = g_val[idx]; }
        int cnt = min(32, end - j);
#pragma unroll 4
        for (int t = 0; t < cnt; t++) {
            int cc   = __shfl_sync(0xffffffffu, c, t);
            float ww = __shfl_sync(0xffffffffu, wv, t);
            float4 xv = row_load4(X, cc, lane);
            acc.x += ww * xv.x;
            acc.y += ww * xv.y;
            acc.z += ww * xv.z;
            acc.w += ww * xv.w;
        }
    }
    row_store4(Y, row, lane, acc);
}

// ---------------- launch ----------------------------------------------------
extern "C" void kernel_launch(void* const* d_in, const int* in_sizes, int n_in,
                              void* d_out, int out_size) {
    const float* x   = (const float*)d_in[0];
    const void*  ei  = d_in[1];
    const float* W1  = (const float*)d_in[2];
    const float* b1  = (const float*)d_in[3];
    const float* g1  = (const float*)d_in[4];
    const float* be1 = (const float*)d_in[5];
    const float* Wc  = (const float*)d_in[6];
    const float* bc  = (const float*)d_in[7];
    const float* g2  = (const float*)d_in[8];
    const float* be2 = (const float*)d_in[9];
    const float* W2  = (const float*)d_in[10];
    const float* b2  = (const float*)d_in[11];
    float* out = (float*)d_out;

    __half *h0, *h1, *W1h, *Wch, *W2h;
    cudaGetSymbolAddress((void**)&h0, g_h0);
    cudaGetSymbolAddress((void**)&h1, g_h1);
    cudaGetSymbolAddress((void**)&W1h, g_W1h);
    cudaGetSymbolAddress((void**)&Wch, g_Wch);
    cudaGetSymbolAddress((void**)&W2h, g_W2h);

    const int smem128 = 128 * 128 * 4;     // 65536 (C stage dominates)
    const int smem64  = 128 * 64 * 4;      // 32768 (C stage dominates)

    static cudaStream_t s2 = nullptr;
    static cudaEvent_t evFork = nullptr, evJoin = nullptr, evH1 = nullptr, evH2 = nullptr;
    if (!s2) {
        cudaFuncSetAttribute(hgemm_kernel<128, 1, float, __half>,
                             cudaFuncAttributeMaxDynamicSharedMemorySize, smem128);
        cudaFuncSetAttribute(hgemm_kernel<128, 1, __half, __half>,
                             cudaFuncAttributeMaxDynamicSharedMemorySize, smem128);
        cudaFuncSetAttribute(hgemm_kernel<64, 2, __half, float>,
                             cudaFuncAttributeMaxDynamicSharedMemorySize, smem64);
        cudaStreamCreateWithFlags(&s2, cudaStreamNonBlocking);
        cudaEventCreateWithFlags(&evFork, cudaEventDisableTiming);
        cudaEventCreateWithFlags(&evJoin, cudaEventDisableTiming);
        cudaEventCreateWithFlags(&evH1, cudaEventDisableTiming);
        cudaEventCreateWithFlags(&evH2, cudaEventDisableTiming);
    }

    const int nodeGrid = (N_NODES + 255) / 256;
    const int edgeGrid = (N_EDGES + 255) / 256;
    const int rpGrid = (N_NODES + 1 + 255) / 256;
    const int w1Grid = (IN_CH * HID + 255) / 256;
    const int wc2Grid = (HID * HID + 255) / 256;

    const int tilesA = SPLIT / 128;                        // 391
    const int tilesB = (N_NODES - SPLIT + 127) / 128;      // 391
    const int hopGridA = (SPLIT * 32 + 255) / 256;
    const int hopGridB = ((N_NODES - SPLIT) * 32 + 255) / 256;
    const int hopGridFull = (N_NODES * 32 + 255) / 256;

    // ---- fork: CSR build + Wc/W2 conversion on s2 ----
    cudaEventRecord(evFork, 0);
    cudaStreamWaitEvent(s2, evFork, 0);

    zero_probe_kernel<<<nodeGrid, 256, 0, s2>>>((const int*)ei);
    count_kernel<<<edgeGrid, 256, 0, s2>>>(ei);
    part_dinv_kernel<<<SCAN_BLK, 256, 0, s2>>>();
    pscan_kernel<<<1, 512, 0, s2>>>();
    rowptr_scan_kernel<<<rpGrid, 256, 0, s2>>>();
    fill_kernel<<<edgeGrid, 256, 0, s2>>>(ei);
    convert_wc2_kernel<<<wc2Grid, 256, 0, s2>>>(Wc, W2);
    cudaEventRecord(evJoin, s2);

    // main: W1 -> fp16; GEMM1 -> h0 (fused GELU+LN epilogue)
    convert_w1_kernel<<<w1Grid, 256>>>(W1);
    hgemm_kernel<128, 1, float, __half><<<M_TILES, 256, smem128>>>(
        x, W1h, b1, g1, be1, h0, 0, N_NODES, IN_CH);

    // join: hop1 needs CSR + h0
    cudaStreamWaitEvent(0, evJoin, 0);
    spmm_hop_kernel<<<hopGridFull, 256>>>(h0, h1, 0, N_NODES);   // hop1
    cudaEventRecord(evH1, 0);

    // hop2 half B on s2, concurrent with main's half-A hop2+tail
    cudaStreamWaitEvent(s2, evH1, 0);
    spmm_hop_kernel<<<hopGridB, 256, 0, s2>>>(h1, h0, SPLIT, N_NODES);
    cudaEventRecord(evH2, s2);

    // main: hop2 half A, then tail for half A
    spmm_hop_kernel<<<hopGridA, 256>>>(h1, h0, 0, SPLIT);
    hgemm_kernel<128, 1, __half, __half><<<tilesA, 256, smem128>>>(
        h0, Wch, bc, g2, be2, h1, 0, SPLIT, HID);
    hgemm_kernel<64, 2, __half, float><<<tilesA, 256, smem64>>>(
        h1, W2h, b2, nullptr, nullptr, out, 0, SPLIT, HID);

    // wait for half-B hop2, then tail for half B
    cudaStreamWaitEvent(0, evH2, 0);
    hgemm_kernel<128, 1, __half, __half><<<tilesB, 256, smem128>>>(
        h0, Wch, bc, g2, be2, h1, SPLIT, N_NODES, HID);
    hgemm_kernel<64, 2, __half, float><<<tilesB, 256, smem64>>>(
        h1, W2h, b2, nullptr, nullptr, out, SPLIT, N_NODES, HID);
}

// round 14
// speedup vs baseline: 1.0342x; 1.0342x over previous
#include <cuda_runtime.h>
#include <cuda_fp16.h>
#include <mma.h>
#include <cstdint>

using namespace nvcuda;

#define N_NODES 100000
#define N_EDGES 1600000
#define IN_CH   512
#define HID     128
#define OUT_CH  64
#define SCAN_BLK ((N_NODES + 255) / 256)   // 391
#define M_TILES  ((N_NODES + 127) / 128)   // 782
#define M_PAD    (M_TILES * 128)           // 100096

#define LDAH 40          // A stage: 32 + 8 pad (halfs)

// ---------------- scratch (device globals; no allocation allowed) ----------
__device__ __half g_h0[(size_t)M_PAD * HID];
__device__ __half g_h1[(size_t)M_PAD * HID];
__device__ __half g_W1h[IN_CH * HID];
__device__ __half g_Wch[HID * HID];
__device__ __half g_W2h[HID * OUT_CH];
__device__ float  g_dinv[N_NODES];
__device__ int    g_count[N_NODES];
__device__ int    g_fill[N_NODES];
__device__ int    g_rowptr[N_NODES + 1];
__device__ int2   g_colval[N_EDGES];       // packed (col, val-bits)
__device__ int    g_part[SCAN_BLK];
__device__ int    g_pscan[SCAN_BLK];
__device__ int    g_is64;

// ---------------- helpers --------------------------------------------------
__device__ __forceinline__ float gelu_exact(float v) {
    return 0.5f * v * (1.0f + erff(v * 0.7071067811865476f));
}

__device__ __forceinline__ int clampN(int v) {
    return min(max(v, 0), N_NODES - 1);
}

__device__ __forceinline__ int edge_at(const void* ei, int k) {
    if (g_is64) return (int)((const long long*)ei)[k];
    return ((const int*)ei)[k];
}

__device__ __forceinline__ void cp_async16(void* smem, const void* g) {
    uint32_t s = (uint32_t)__cvta_generic_to_shared(smem);
    asm volatile("cp.async.cg.shared.global [%0], [%1], 16;"
                 :: "r"(s), "l"(g));
}

__device__ __forceinline__ uint2 f4_to_h4(float4 v) {
    __half2 a = __floats2half2_rn(v.x, v.y);
    __half2 b = __floats2half2_rn(v.z, v.w);
    uint2 u;
    u.x = *reinterpret_cast<uint32_t*>(&a);
    u.y = *reinterpret_cast<uint32_t*>(&b);
    return u;
}

__device__ __forceinline__ float4 row_load4(const __half* X, int row, int lane) {
    uint2 u = ((const uint2*)(X + (size_t)row * HID))[lane];
    __half2 a = *reinterpret_cast<__half2*>(&u.x);
    __half2 b = *reinterpret_cast<__half2*>(&u.y);
    float2 f0 = __half22float2(a);
    float2 f1 = __half22float2(b);
    return make_float4(f0.x, f0.y, f1.x, f1.y);
}
__device__ __forceinline__ void row_store4(float* Y, int row, int lane, float4 v) {
    ((float4*)(Y + (size_t)row * HID))[lane] = v;
}
__device__ __forceinline__ void row_store4(__half* Y, int row, int lane, float4 v) {
    ((uint2*)(Y + (size_t)row * HID))[lane] = f4_to_h4(v);
}

// ---------------- fp16 HMMA GEMM, 2-stage double buffer ---------------------
// BM=128, BK=32, 8 warps, 2 CTAs/SM.
// AT=float : A loaded via LDG, converted to fp16, STS (register staging).
// AT=half  : A loaded via cp.async (already fp16).
// MODE 1: fused bias + exact-GELU + LayerNorm epilogue -> OutT.
// MODE 2: staged bias-only epilogue (fp32, guarded) for d_out.
template <int BN, int MODE, typename AT, typename OutT>
__global__ void __launch_bounds__(256, 2)
hgemm_kernel(const AT* __restrict__ A,
             const __half* __restrict__ Bm,
             const float* __restrict__ bias,
             const float* __restrict__ gamma,
             const float* __restrict__ beta,
             OutT* __restrict__ C,
             int M, int K) {
    constexpr int BM = 128, BK = 32;
    constexpr int LDBH = BN + 8;
    constexpr int WN = (BN == 128) ? 4 : 2;
    constexpr int ASZ = BM * LDAH;        // halfs per A stage
    constexpr int BSZ = BK * LDBH;        // halfs per B stage
    constexpr bool A_F32 = (sizeof(AT) == 4);

    extern __shared__ __align__(16) char dsm[];
    __half* Ah = (__half*)dsm;            // [2][ASZ]
    __half* Bh = Ah + 2 * ASZ;            // [2][BSZ]
    float*  Cs = (float*)dsm;             // reused after mainloop

    const int tid   = threadIdx.x;
    const int wid   = tid >> 5;
    const int lane  = tid & 31;
    const int warpM = wid & 3;
    const int warpN = wid >> 2;
    const int rowBase = blockIdx.x * BM;
    const int kIters = K / BK;

    // B tile via cp.async: BK rows x BN halfs
    auto loadB = [&](int k0, int buf) {
        constexpr int CH = BK * BN / 8;   // 16B chunks: 512 (BN=128) / 256
#pragma unroll
        for (int i = 0; i < (CH + 255) / 256; i++) {
            int lin = tid + i * 256;
            if (CH < 256 || lin < CH) {
                int r = lin / (BN / 8);
                int c8 = (lin % (BN / 8)) * 8;
                cp_async16(&Bh[buf * BSZ + r * LDBH + c8],
                           Bm + (size_t)(k0 + r) * BN + c8);
            }
        }
    };

    // A tile, fp32 source: 4 float4 per thread (128x32 fp32)
    float4 aregs[4];
    auto loadA_f32 = [&](int k0) {
#pragma unroll
        for (int i = 0; i < 4; i++) {
            int lin = tid + i * 256;
            int r = lin >> 3;
            int c4 = (lin & 7) * 4;
            int gr = min(rowBase + r, M - 1);
            aregs[i] = *(const float4*)((const float*)A + (size_t)gr * K + k0 + c4);
        }
    };
    auto stsA_f32 = [&](int buf) {
#pragma unroll
        for (int i = 0; i < 4; i++) {
            int lin = tid + i * 256;
            int r = lin >> 3;
            int c4 = (lin & 7) * 4;
            *(uint2*)&Ah[buf * ASZ + r * LDAH + c4] = f4_to_h4(aregs[i]);
        }
    };

    // A tile, fp16 source via cp.async: 128x32 halfs = 512 chunks, 2/thread
    auto loadA_f16 = [&](int k0, int buf) {
#pragma unroll
        for (int i = 0; i < 2; i++) {
            int lin = tid + i * 256;
            int r = lin >> 2;
            int c8 = (lin & 3) * 8;
            int gr = min(rowBase + r, M - 1);
            cp_async16(&Ah[buf * ASZ + r * LDAH + c8],
                       (const __half*)A + (size_t)gr * K + k0 + c8);
        }
    };

    wmma::fragment<wmma::accumulator, 16, 16, 16, float> acc[2][WN];
#pragma unroll
    for (int i = 0; i < 2; i++)
#pragma unroll
        for (int j = 0; j < WN; j++) wmma::fill_fragment(acc[i][j], 0.0f);

    // prologue
    if (A_F32) {
        loadA_f32(0);
        loadB(0, 0);
        asm volatile("cp.async.commit_group;");
        stsA_f32(0);
    } else {
        loadA_f16(0, 0);
        loadB(0, 0);
        asm volatile("cp.async.commit_group;");
    }
    asm volatile("cp.async.wait_group 0;");
    __syncthreads();

    for (int it = 0; it < kIters; it++) {
        const int cur = it & 1;
        const bool more = (it + 1 < kIters);
        if (more) {
            if (A_F32) {
                loadA_f32((it + 1) * BK);
                loadB((it + 1) * BK, cur ^ 1);
            } else {
                loadA_f16((it + 1) * BK, cur ^ 1);
                loadB((it + 1) * BK, cur ^ 1);
            }
            asm volatile("cp.async.commit_group;");
        }

        const __half* as = Ah + cur * ASZ;
        const __half* bs = Bh + cur * BSZ;
#pragma unroll
        for (int kk = 0; kk < BK; kk += 16) {
            wmma::fragment<wmma::matrix_a, 16, 16, 16, __half, wmma::row_major> af[2];
#pragma unroll
            for (int i = 0; i < 2; i++)
                wmma::load_matrix_sync(af[i], as + (warpM * 32 + i * 16) * LDAH + kk, LDAH);
#pragma unroll
            for (int j = 0; j < WN; j++) {
                wmma::fragment<wmma::matrix_b, 16, 16, 16, __half, wmma::row_major> bf;
                wmma::load_matrix_sync(bf, bs + kk * LDBH + warpN * WN * 16 + j * 16, LDBH);
                wmma::mma_sync(acc[0][j], af[0], bf, acc[0][j]);
                wmma::mma_sync(acc[1][j], af[1], bf, acc[1][j]);
            }
        }

        if (more) {
            if (A_F32) stsA_f32(cur ^ 1);
            asm volatile("cp.async.wait_group 0;");
            __syncthreads();
        }
    }

    __syncthreads();   // all warps done with tiles before smem reuse

    // ---- stage C tile to smem ----
#pragma unroll
    for (int i = 0; i < 2; i++)
#pragma unroll
        for (int j = 0; j < WN; j++) {
            int r = warpM * 32 + i * 16;
            int c = warpN * WN * 16 + j * 16;
            wmma::store_matrix_sync(Cs + (size_t)r * BN + c, acc[i][j], BN,
                                    wmma::mem_row_major);
        }
    __syncthreads();

    if (MODE == 1) {
        float4 bb = ((const float4*)bias)[lane];
        float4 gg = ((const float4*)gamma)[lane];
        float4 be = ((const float4*)beta)[lane];
#pragma unroll
        for (int i = 0; i < 16; i++) {
            int r = wid * 16 + i;
            int gr = rowBase + r;
            float4 v = ((const float4*)(Cs + (size_t)r * BN))[lane];
            v.x = gelu_exact(v.x + bb.x);
            v.y = gelu_exact(v.y + bb.y);
            v.z = gelu_exact(v.z + bb.z);
            v.w = gelu_exact(v.w + bb.w);
            float s  = v.x + v.y + v.z + v.w;
            float sq = v.x * v.x + v.y * v.y + v.z * v.z + v.w * v.w;
#pragma unroll
            for (int off = 16; off > 0; off >>= 1) {
                s  += __shfl_xor_sync(0xffffffffu, s, off);
                sq += __shfl_xor_sync(0xffffffffu, sq, off);
            }
            float mu   = s * (1.0f / HID);
            float var  = sq * (1.0f / HID) - mu * mu;
            float rstd = rsqrtf(var + 1e-5f);
            float4 o;
            o.x = (v.x - mu) * rstd * gg.x + be.x;
            o.y = (v.y - mu) * rstd * gg.y + be.y;
            o.z = (v.z - mu) * rstd * gg.z + be.z;
            o.w = (v.w - mu) * rstd * gg.w + be.w;
            if (gr < M) row_store4(C, gr, lane, o);
        }
    } else {
        constexpr int C4 = BM * BN / 4;
#pragma unroll
        for (int i = 0; i < C4 / 256; i++) {
            int lin = tid + i * 256;
            int r = lin / (BN / 4);
            int c = (lin % (BN / 4)) * 4;
            int gr = rowBase + r;
            if (gr < M) {
                float4 v = *(float4*)(Cs + (size_t)r * BN + c);
                v.x += bias[c + 0];
                v.y += bias[c + 1];
                v.z += bias[c + 2];
                v.w += bias[c + 3];
                *(float4*)((float*)C + (size_t)gr * BN + c) = v;
            }
        }
    }
}

// ---------------- weight conversion ----------------------------------------
__global__ void convert_weights_kernel(const float* __restrict__ W1,
                                       const float* __restrict__ Wc,
                                       const float* __restrict__ W2) {
    int i = blockIdx.x * blockDim.x + threadIdx.x;
    if (i < IN_CH * HID) g_W1h[i] = __float2half_rn(W1[i]);
    if (i < HID * HID)   g_Wch[i] = __float2half_rn(Wc[i]);
    if (i < HID * OUT_CH) g_W2h[i] = __float2half_rn(W2[i]);
}

// ---------------- CSR build (side stream, overlapped with GEMM1) -----------
__global__ void zero_probe_kernel(const int* __restrict__ a) {
    int i = blockIdx.x * blockDim.x + threadIdx.x;
    if (i < N_NODES) { g_count[i] = 0; g_fill[i] = 0; }
    if (blockIdx.x == 0 && threadIdx.x == 0) {
        int all0 = 1;
        for (int k = 1; k < 64; k += 2) all0 &= (a[k] == 0);
        g_is64 = all0;
    }
}

__global__ void count_kernel(const void* __restrict__ ei) {
    int e = blockIdx.x * blockDim.x + threadIdx.x;
    if (e >= N_EDGES) return;
    int d = clampN(edge_at(ei, N_EDGES + e));
    atomicAdd(&g_count[d], 1);
}

__global__ void part_dinv_kernel() {
    __shared__ int sdata[256];
    int tid = threadIdx.x;
    int idx = blockIdx.x * 256 + tid;
    int c = (idx < N_NODES) ? g_count[idx] : 0;
    if (idx < N_NODES) g_dinv[idx] = rsqrtf((float)(c + 1));  // +1 self-loop
    sdata[tid] = c;
    __syncthreads();
    for (int s = 128; s > 0; s >>= 1) {
        if (tid < s) sdata[tid] += sdata[tid + s];
        __syncthreads();
    }
    if (tid == 0) g_part[blockIdx.x] = sdata[0];
}

__global__ void pscan_kernel() {
    __shared__ int wsums[16];
    int tid = threadIdx.x;
    int lane = tid & 31;
    int wid = tid >> 5;
    int v = (tid < SCAN_BLK) ? g_part[tid] : 0;
    int incl = v;
#pragma unroll
    for (int off = 1; off < 32; off <<= 1) {
        int n = __shfl_up_sync(0xffffffffu, incl, off);
        if (lane >= off) incl += n;
    }
    if (lane == 31) wsums[wid] = incl;
    __syncthreads();
    if (tid == 0) {
        int s = 0;
#pragma unroll
        for (int i = 0; i < 16; i++) { int t = wsums[i]; wsums[i] = s; s += t; }
    }
    __syncthreads();
    if (tid < SCAN_BLK) g_pscan[tid] = incl - v + wsums[wid];
}

__global__ void rowptr_scan_kernel() {
    __shared__ int wsums[8];
    int tid = threadIdx.x;
    int lane = tid & 31;
    int wid = tid >> 5;
    int idx = blockIdx.x * 256 + tid;
    int v = (idx < N_NODES) ? g_count[idx] : 0;
    int incl = v;
#pragma unroll
    for (int off = 1; off < 32; off <<= 1) {
        int n = __shfl_up_sync(0xffffffffu, incl, off);
        if (lane >= off) incl += n;
    }
    if (lane == 31) wsums[wid] = incl;
    __syncthreads();
    if (tid == 0) {
        int s = 0;
#pragma unroll
        for (int i = 0; i < 8; i++) { int t = wsums[i]; wsums[i] = s; s += t; }
    }
    __syncthreads();
    int excl = incl - v + wsums[wid] + g_pscan[blockIdx.x];
    if (idx <= N_NODES) g_rowptr[idx] = excl;
}

__global__ void fill_kernel(const void* __restrict__ ei) {
    int e = blockIdx.x * blockDim.x + threadIdx.x;
    if (e >= N_EDGES) return;
    int s = clampN(edge_at(ei, e));
    int d = clampN(edge_at(ei, N_EDGES + e));
    int pos = g_rowptr[d] + atomicAdd(&g_fill[d], 1);
    pos = min(max(pos, 0), N_EDGES - 1);
    float w = g_dinv[s] * g_dinv[d];
    g_colval[pos] = make_int2(s, __float_as_int(w));
}

// ---------------- pull-mode SpMM hop (warp per dst row) ---------------------
__global__ void spmm_hop_kernel(const __half* __restrict__ X,
                                __half* __restrict__ Y) {
    int row = (blockIdx.x * blockDim.x + threadIdx.x) >> 5;
    int lane = threadIdx.x & 31;
    if (row >= N_NODES) return;
    int start = g_rowptr[row];
    int end   = g_rowptr[row + 1];
    start = min(max(start, 0), N_EDGES);
    end   = min(max(end, start), N_EDGES);
    float di = g_dinv[row];
    float w0 = di * di;
    float4 v = row_load4(X, row, lane);
    float4 acc;
    acc.x = w0 * v.x; acc.y = w0 * v.y; acc.z = w0 * v.z; acc.w = w0 * v.w;

    for (int j = start; j < end; j += 32) {
        int idx = j + lane;
        int c = 0;
        float wv = 0.0f;
        if (idx < end) {
            int2 cv = g_colval[idx];
            c = clampN(cv.x);
            wv = __int_as_float(cv.y);
        }
        int cnt = min(32, end - j);
#pragma unroll 4
        for (int t = 0; t < cnt; t++) {
            int cc   = __shfl_sync(0xffffffffu, c, t);
            float ww = __shfl_sync(0xffffffffu, wv, t);
            float4 xv = row_load4(X, cc, lane);
            acc.x += ww * xv.x;
            acc.y += ww * xv.y;
            acc.z += ww * xv.z;
            acc.w += ww * xv.w;
        }
    }
    row_store4(Y, row, lane, acc);
}

// ---------------- launch ----------------------------------------------------
extern "C" void kernel_launch(void* const* d_in, const int* in_sizes, int n_in,
                              void* d_out, int out_size) {
    const float* x   = (const float*)d_in[0];
    const void*  ei  = d_in[1];
    const float* W1  = (const float*)d_in[2];
    const float* b1  = (const float*)d_in[3];
    const float* g1  = (const float*)d_in[4];
    const float* be1 = (const float*)d_in[5];
    const float* Wc  = (const float*)d_in[6];
    const float* bc  = (const float*)d_in[7];
    const float* g2  = (const float*)d_in[8];
    const float* be2 = (const float*)d_in[9];
    const float* W2  = (const float*)d_in[10];
    const float* b2  = (const float*)d_in[11];
    float* out = (float*)d_out;

    __half *h0, *h1, *W1h, *Wch, *W2h;
    cudaGetSymbolAddress((void**)&h0, g_h0);
    cudaGetSymbolAddress((void**)&h1, g_h1);
    cudaGetSymbolAddress((void**)&W1h, g_W1h);
    cudaGetSymbolAddress((void**)&Wch, g_Wch);
    cudaGetSymbolAddress((void**)&W2h, g_W2h);

    // dynamic smem: max(tile stages, C stage)
    const int smem128 = 128 * 128 * 4;     // 65536 (C stage dominates)
    const int smem64  = 128 * 64 * 4;      // 32768 (C stage dominates)

    static cudaStream_t s2 = nullptr;
    static cudaEvent_t evFork = nullptr, evJoin = nullptr;
    if (!s2) {
        cudaFuncSetAttribute(hgemm_kernel<128, 1, float, __half>,
                             cudaFuncAttributeMaxDynamicSharedMemorySize, smem128);
        cudaFuncSetAttribute(hgemm_kernel<128, 1, __half, __half>,
                             cudaFuncAttributeMaxDynamicSharedMemorySize, smem128);
        cudaFuncSetAttribute(hgemm_kernel<64, 2, __half, float>,
                             cudaFuncAttributeMaxDynamicSharedMemorySize, smem64);
        cudaStreamCreateWithFlags(&s2, cudaStreamNonBlocking);
        cudaEventCreateWithFlags(&evFork, cudaEventDisableTiming);
        cudaEventCreateWithFlags(&evJoin, cudaEventDisableTiming);
    }

    const int gemmGrid = M_TILES;                        // 782
    const int rowWarpGrid = (N_NODES * 32 + 255) / 256;  // warp per row
    const int nodeGrid = (N_NODES + 255) / 256;
    const int edgeGrid = (N_EDGES + 255) / 256;
    const int rpGrid = (N_NODES + 1 + 255) / 256;
    const int wGrid = (IN_CH * HID + 255) / 256;

    // ---- fork: CSR build on s2, weights+GEMM1 on main (independent) ----
    cudaEventRecord(evFork, 0);
    cudaStreamWaitEvent(s2, evFork, 0);

    zero_probe_kernel<<<nodeGrid, 256, 0, s2>>>((const int*)ei);
    count_kernel<<<edgeGrid, 256, 0, s2>>>(ei);
    part_dinv_kernel<<<SCAN_BLK, 256, 0, s2>>>();
    pscan_kernel<<<1, 512, 0, s2>>>();
    rowptr_scan_kernel<<<rpGrid, 256, 0, s2>>>();
    fill_kernel<<<edgeGrid, 256, 0, s2>>>(ei);
    cudaEventRecord(evJoin, s2);

    // weights -> fp16, then Stage 1: h0 = LN(GELU(x @ W1 + b1)) (fp16 out)
    convert_weights_kernel<<<wGrid, 256>>>(W1, Wc, W2);
    hgemm_kernel<128, 1, float, __half><<<gemmGrid, 256, smem128>>>(
        x, W1h, b1, g1, be1, h0, N_NODES, IN_CH);

    // ---- join: hops need both h0 and CSR ----
    cudaStreamWaitEvent(0, evJoin, 0);

    // Hop 1: h0 -> h1 ; Hop 2: h1 -> h0 (fp32 accumulate, fp16 store)
    spmm_hop_kernel<<<rowWarpGrid, 256>>>(h0, h1);
    spmm_hop_kernel<<<rowWarpGrid, 256>>>(h1, h0);

    // Stage 3: h1 = LN(GELU(h0 @ Wc + bc)); out = h1 @ W2 + b2
    hgemm_kernel<128, 1, __half, __half><<<gemmGrid, 256, smem128>>>(
        h0, Wch, bc, g2, be2, h1, N_NODES, HID);
    hgemm_kernel<64, 2, __half, float><<<gemmGrid, 256, smem64>>>(
        h1, W2h, b2, nullptr, nullptr, out, N_NODES, HID);
}

// round 15
// speedup vs baseline: 1.0459x; 1.0113x over previous
#include <cuda_runtime.h>
#include <cuda_fp16.h>
#include <mma.h>
#include <cstdint>

using namespace nvcuda;

#define N_NODES 100000
#define N_EDGES 1600000
#define IN_CH   512
#define HID     128
#define OUT_CH  64
#define SCAN_BLK ((N_NODES + 255) / 256)   // 391
#define M_TILES  ((N_NODES + 127) / 128)   // 782
#define M_PAD    (M_TILES * 128)           // 100096

#define LDAH 40          // A stage: 32 + 8 pad (halfs)

// ---------------- scratch (device globals; no allocation allowed) ----------
__device__ __half g_h0[(size_t)M_PAD * HID];
__device__ __half g_h1[(size_t)M_PAD * HID];
__device__ __half g_W1h[IN_CH * HID];
__device__ __half g_Wch[HID * HID];
__device__ __half g_W2h[HID * OUT_CH];
__device__ float  g_dinv[N_NODES];
__device__ int    g_cnt2[2 * N_NODES];     // [0..N): count, [N..2N): fill
__device__ int    g_rowptr[N_NODES + 1];
__device__ int2   g_colval[N_EDGES];       // packed (col, val-bits)
__device__ int    g_part[SCAN_BLK];
__device__ int    g_is64;

// ---------------- helpers --------------------------------------------------
__device__ __forceinline__ float gelu_exact(float v) {
    return 0.5f * v * (1.0f + erff(v * 0.7071067811865476f));
}

__device__ __forceinline__ int clampN(int v) {
    return min(max(v, 0), N_NODES - 1);
}

__device__ __forceinline__ int edge_at(const void* ei, int k) {
    if (g_is64) return (int)((const long long*)ei)[k];
    return ((const int*)ei)[k];
}

__device__ __forceinline__ void cp_async16(void* smem, const void* g) {
    uint32_t s = (uint32_t)__cvta_generic_to_shared(smem);
    asm volatile("cp.async.cg.shared.global [%0], [%1], 16;"
                 :: "r"(s), "l"(g));
}

__device__ __forceinline__ uint2 f4_to_h4(float4 v) {
    __half2 a = __floats2half2_rn(v.x, v.y);
    __half2 b = __floats2half2_rn(v.z, v.w);
    uint2 u;
    u.x = *reinterpret_cast<uint32_t*>(&a);
    u.y = *reinterpret_cast<uint32_t*>(&b);
    return u;
}

__device__ __forceinline__ float4 row_load4(const __half* X, int row, int lane) {
    uint2 u = ((const uint2*)(X + (size_t)row * HID))[lane];
    __half2 a = *reinterpret_cast<__half2*>(&u.x);
    __half2 b = *reinterpret_cast<__half2*>(&u.y);
    float2 f0 = __half22float2(a);
    float2 f1 = __half22float2(b);
    return make_float4(f0.x, f0.y, f1.x, f1.y);
}
__device__ __forceinline__ void row_store4(float* Y, int row, int lane, float4 v) {
    ((float4*)(Y + (size_t)row * HID))[lane] = v;
}
__device__ __forceinline__ void row_store4(__half* Y, int row, int lane, float4 v) {
    ((uint2*)(Y + (size_t)row * HID))[lane] = f4_to_h4(v);
}

// ---------------- fp16 HMMA GEMM, 2-stage double buffer ---------------------
// BM=128, BK=32, 8 warps, 2 CTAs/SM.
// AT=float : A loaded via LDG, converted to fp16, STS (register staging).
// AT=half  : A loaded via cp.async (already fp16).
// MODE 1: fused bias + exact-GELU + LayerNorm epilogue -> OutT.
// MODE 2: staged bias-only epilogue (fp32, guarded) for d_out.
template <int BN, int MODE, typename AT, typename OutT>
__global__ void __launch_bounds__(256, 2)
hgemm_kernel(const AT* __restrict__ A,
             const __half* __restrict__ Bm,
             const float* __restrict__ bias,
             const float* __restrict__ gamma,
             const float* __restrict__ beta,
             OutT* __restrict__ C,
             int M, int K) {
    constexpr int BM = 128, BK = 32;
    constexpr int LDBH = BN + 8;
    constexpr int WN = (BN == 128) ? 4 : 2;
    constexpr int ASZ = BM * LDAH;        // halfs per A stage
    constexpr int BSZ = BK * LDBH;        // halfs per B stage
    constexpr bool A_F32 = (sizeof(AT) == 4);

    extern __shared__ __align__(16) char dsm[];
    __half* Ah = (__half*)dsm;            // [2][ASZ]
    __half* Bh = Ah + 2 * ASZ;            // [2][BSZ]
    float*  Cs = (float*)dsm;             // reused after mainloop

    const int tid   = threadIdx.x;
    const int wid   = tid >> 5;
    const int lane  = tid & 31;
    const int warpM = wid & 3;
    const int warpN = wid >> 2;
    const int rowBase = blockIdx.x * BM;
    const int kIters = K / BK;

    // B tile via cp.async: BK rows x BN halfs
    auto loadB = [&](int k0, int buf) {
        constexpr int CH = BK * BN / 8;   // 16B chunks: 512 (BN=128) / 256
#pragma unroll
        for (int i = 0; i < (CH + 255) / 256; i++) {
            int lin = tid + i * 256;
            if (CH < 256 || lin < CH) {
                int r = lin / (BN / 8);
                int c8 = (lin % (BN / 8)) * 8;
                cp_async16(&Bh[buf * BSZ + r * LDBH + c8],
                           Bm + (size_t)(k0 + r) * BN + c8);
            }
        }
    };

    // A tile, fp32 source: 4 float4 per thread (128x32 fp32)
    float4 aregs[4];
    auto loadA_f32 = [&](int k0) {
#pragma unroll
        for (int i = 0; i < 4; i++) {
            int lin = tid + i * 256;
            int r = lin >> 3;
            int c4 = (lin & 7) * 4;
            int gr = min(rowBase + r, M - 1);
            aregs[i] = *(const float4*)((const float*)A + (size_t)gr * K + k0 + c4);
        }
    };
    auto stsA_f32 = [&](int buf) {
#pragma unroll
        for (int i = 0; i < 4; i++) {
            int lin = tid + i * 256;
            int r = lin >> 3;
            int c4 = (lin & 7) * 4;
            *(uint2*)&Ah[buf * ASZ + r * LDAH + c4] = f4_to_h4(aregs[i]);
        }
    };

    // A tile, fp16 source via cp.async: 128x32 halfs = 512 chunks, 2/thread
    auto loadA_f16 = [&](int k0, int buf) {
#pragma unroll
        for (int i = 0; i < 2; i++) {
            int lin = tid + i * 256;
            int r = lin >> 2;
            int c8 = (lin & 3) * 8;
            int gr = min(rowBase + r, M - 1);
            cp_async16(&Ah[buf * ASZ + r * LDAH + c8],
                       (const __half*)A + (size_t)gr * K + k0 + c8);
        }
    };

    wmma::fragment<wmma::accumulator, 16, 16, 16, float> acc[2][WN];
#pragma unroll
    for (int i = 0; i < 2; i++)
#pragma unroll
        for (int j = 0; j < WN; j++) wmma::fill_fragment(acc[i][j], 0.0f);

    // prologue
    if (A_F32) {
        loadA_f32(0);
        loadB(0, 0);
        asm volatile("cp.async.commit_group;");
        stsA_f32(0);
    } else {
        loadA_f16(0, 0);
        loadB(0, 0);
        asm volatile("cp.async.commit_group;");
    }
    asm volatile("cp.async.wait_group 0;");
    __syncthreads();

    for (int it = 0; it < kIters; it++) {
        const int cur = it & 1;
        const bool more = (it + 1 < kIters);
        if (more) {
            if (A_F32) {
                loadA_f32((it + 1) * BK);
                loadB((it + 1) * BK, cur ^ 1);
            } else {
                loadA_f16((it + 1) * BK, cur ^ 1);
                loadB((it + 1) * BK, cur ^ 1);
            }
            asm volatile("cp.async.commit_group;");
        }

        const __half* as = Ah + cur * ASZ;
        const __half* bs = Bh + cur * BSZ;
#pragma unroll
        for (int kk = 0; kk < BK; kk += 16) {
            wmma::fragment<wmma::matrix_a, 16, 16, 16, __half, wmma::row_major> af[2];
#pragma unroll
            for (int i = 0; i < 2; i++)
                wmma::load_matrix_sync(af[i], as + (warpM * 32 + i * 16) * LDAH + kk, LDAH);
#pragma unroll
            for (int j = 0; j < WN; j++) {
                wmma::fragment<wmma::matrix_b, 16, 16, 16, __half, wmma::row_major> bf;
                wmma::load_matrix_sync(bf, bs + kk * LDBH + warpN * WN * 16 + j * 16, LDBH);
                wmma::mma_sync(acc[0][j], af[0], bf, acc[0][j]);
                wmma::mma_sync(acc[1][j], af[1], bf, acc[1][j]);
            }
        }

        if (more) {
            if (A_F32) stsA_f32(cur ^ 1);
            asm volatile("cp.async.wait_group 0;");
            __syncthreads();
        }
    }

    __syncthreads();   // all warps done with tiles before smem reuse

    // ---- stage C tile to smem ----
#pragma unroll
    for (int i = 0; i < 2; i++)
#pragma unroll
        for (int j = 0; j < WN; j++) {
            int r = warpM * 32 + i * 16;
            int c = warpN * WN * 16 + j * 16;
            wmma::store_matrix_sync(Cs + (size_t)r * BN + c, acc[i][j], BN,
                                    wmma::mem_row_major);
        }
    __syncthreads();

    if (MODE == 1) {
        float4 bb = ((const float4*)bias)[lane];
        float4 gg = ((const float4*)gamma)[lane];
        float4 be = ((const float4*)beta)[lane];
#pragma unroll
        for (int i = 0; i < 16; i++) {
            int r = wid * 16 + i;
            int gr = rowBase + r;
            float4 v = ((const float4*)(Cs + (size_t)r * BN))[lane];
            v.x = gelu_exact(v.x + bb.x);
            v.y = gelu_exact(v.y + bb.y);
            v.z = gelu_exact(v.z + bb.z);
            v.w = gelu_exact(v.w + bb.w);
            float s  = v.x + v.y + v.z + v.w;
            float sq = v.x * v.x + v.y * v.y + v.z * v.z + v.w * v.w;
#pragma unroll
            for (int off = 16; off > 0; off >>= 1) {
                s  += __shfl_xor_sync(0xffffffffu, s, off);
                sq += __shfl_xor_sync(0xffffffffu, sq, off);
            }
            float mu   = s * (1.0f / HID);
            float var  = sq * (1.0f / HID) - mu * mu;
            float rstd = rsqrtf(var + 1e-5f);
            float4 o;
            o.x = (v.x - mu) * rstd * gg.x + be.x;
            o.y = (v.y - mu) * rstd * gg.y + be.y;
            o.z = (v.z - mu) * rstd * gg.z + be.z;
            o.w = (v.w - mu) * rstd * gg.w + be.w;
            if (gr < M) row_store4(C, gr, lane, o);
        }
    } else {
        constexpr int C4 = BM * BN / 4;
#pragma unroll
        for (int i = 0; i < C4 / 256; i++) {
            int lin = tid + i * 256;
            int r = lin / (BN / 4);
            int c = (lin % (BN / 4)) * 4;
            int gr = rowBase + r;
            if (gr < M) {
                float4 v = *(float4*)(Cs + (size_t)r * BN + c);
                v.x += bias[c + 0];
                v.y += bias[c + 1];
                v.z += bias[c + 2];
                v.w += bias[c + 3];
                *(float4*)((float*)C + (size_t)gr * BN + c) = v;
            }
        }
    }
}

// ---------------- weight conversion ----------------------------------------
__global__ void convert_weights_kernel(const float* __restrict__ W1,
                                       const float* __restrict__ Wc,
                                       const float* __restrict__ W2) {
    int i = blockIdx.x * blockDim.x + threadIdx.x;
    if (i < IN_CH * HID) g_W1h[i] = __float2half_rn(W1[i]);
    if (i < HID * HID)   g_Wch[i] = __float2half_rn(W2 != nullptr ? Wc[i] : Wc[i]);
    if (i < HID * OUT_CH) g_W2h[i] = __float2half_rn(W2[i]);
}

// ---------------- CSR build (side stream, overlapped with GEMM1) -----------
// tiny dtype probe (int64 node ids have zero high words)
__global__ void probe_kernel(const int* __restrict__ a) {
    if (blockIdx.x == 0 && threadIdx.x == 0) {
        int all0 = 1;
        for (int k = 1; k < 64; k += 2) all0 &= (a[k] == 0);
        g_is64 = all0;
    }
}

__global__ void count_kernel(const void* __restrict__ ei) {
    int e = blockIdx.x * blockDim.x + threadIdx.x;
    if (e >= N_EDGES) return;
    int d = clampN(edge_at(ei, N_EDGES + e));
    atomicAdd(&g_cnt2[d], 1);
}

__global__ void part_dinv_kernel() {
    __shared__ int sdata[256];
    int tid = threadIdx.x;
    int idx = blockIdx.x * 256 + tid;
    int c = (idx < N_NODES) ? g_cnt2[idx] : 0;
    if (idx < N_NODES) g_dinv[idx] = rsqrtf((float)(c + 1));  // +1 self-loop
    sdata[tid] = c;
    __syncthreads();
    for (int s = 128; s > 0; s >>= 1) {
        if (tid < s) sdata[tid] += sdata[tid + s];
        __syncthreads();
    }
    if (tid == 0) g_part[blockIdx.x] = sdata[0];
}

// rowptr scan with inlined cross-tile prefix: each block sums g_part[0..b)
__global__ void rowptr_scan_kernel() {
    __shared__ int sred[256];
    __shared__ int wsums[8];
    __shared__ int blockPre;
    int tid = threadIdx.x;
    int lane = tid & 31;
    int wid = tid >> 5;
    int b = blockIdx.x;

    // cross-tile prefix: sum of g_part[0..b)
    int p = 0;
    for (int i = tid; i < b; i += 256) p += g_part[i];
    sred[tid] = p;
    __syncthreads();
    for (int s = 128; s > 0; s >>= 1) {
        if (tid < s) sred[tid] += sred[tid + s];
        __syncthreads();
    }
    if (tid == 0) blockPre = sred[0];
    __syncthreads();

    int idx = b * 256 + tid;
    int v = (idx < N_NODES) ? g_cnt2[idx] : 0;
    int incl = v;
#pragma unroll
    for (int off = 1; off < 32; off <<= 1) {
        int n = __shfl_up_sync(0xffffffffu, incl, off);
        if (lane >= off) incl += n;
    }
    if (lane == 31) wsums[wid] = incl;
    __syncthreads();
    if (tid == 0) {
        int s = 0;
#pragma unroll
        for (int i = 0; i < 8; i++) { int t = wsums[i]; wsums[i] = s; s += t; }
    }
    __syncthreads();
    int excl = incl - v + wsums[wid] + blockPre;
    if (idx <= N_NODES) g_rowptr[idx] = excl;
}

__global__ void fill_kernel(const void* __restrict__ ei) {
    int e = blockIdx.x * blockDim.x + threadIdx.x;
    if (e >= N_EDGES) return;
    int s = clampN(edge_at(ei, e));
    int d = clampN(edge_at(ei, N_EDGES + e));
    int pos = g_rowptr[d] + atomicAdd(&g_cnt2[N_NODES + d], 1);
    pos = min(max(pos, 0), N_EDGES - 1);
    float w = g_dinv[s] * g_dinv[d];
    g_colval[pos] = make_int2(s, __float_as_int(w));
}

// ---------------- pull-mode SpMM hop (warp per dst row) ---------------------
__global__ void spmm_hop_kernel(const __half* __restrict__ X,
                                __half* __restrict__ Y) {
    int row = (blockIdx.x * blockDim.x + threadIdx.x) >> 5;
    int lane = threadIdx.x & 31;
    if (row >= N_NODES) return;
    int start = g_rowptr[row];
    int end   = g_rowptr[row + 1];
    start = min(max(start, 0), N_EDGES);
    end   = min(max(end, start), N_EDGES);
    float di = g_dinv[row];
    float w0 = di * di;
    float4 v = row_load4(X, row, lane);
    float4 acc;
    acc.x = w0 * v.x; acc.y = w0 * v.y; acc.z = w0 * v.z; acc.w = w0 * v.w;

    for (int j = start; j < end; j += 32) {
        int idx = j + lane;
        int c = 0;
        float wv = 0.0f;
        if (idx < end) {
            int2 cv = g_colval[idx];
            c = clampN(cv.x);
            wv = __int_as_float(cv.y);
        }
        int cnt = min(32, end - j);
#pragma unroll 4
        for (int t = 0; t < cnt; t++) {
            int cc   = __shfl_sync(0xffffffffu, c, t);
            float ww = __shfl_sync(0xffffffffu, wv, t);
            float4 xv = row_load4(X, cc, lane);
            acc.x += ww * xv.x;
            acc.y += ww * xv.y;
            acc.z += ww * xv.z;
            acc.w += ww * xv.w;
        }
    }
    row_store4(Y, row, lane, acc);
}

// ---------------- launch ----------------------------------------------------
extern "C" void kernel_launch(void* const* d_in, const int* in_sizes, int n_in,
                              void* d_out, int out_size) {
    const float* x   = (const float*)d_in[0];
    const void*  ei  = d_in[1];
    const float* W1  = (const float*)d_in[2];
    const float* b1  = (const float*)d_in[3];
    const float* g1  = (const float*)d_in[4];
    const float* be1 = (const float*)d_in[5];
    const float* Wc  = (const float*)d_in[6];
    const float* bc  = (const float*)d_in[7];
    const float* g2  = (const float*)d_in[8];
    const float* be2 = (const float*)d_in[9];
    const float* W2  = (const float*)d_in[10];
    const float* b2  = (const float*)d_in[11];
    float* out = (float*)d_out;

    __half *h0, *h1, *W1h, *Wch, *W2h;
    int* cnt2;
    cudaGetSymbolAddress((void**)&h0, g_h0);
    cudaGetSymbolAddress((void**)&h1, g_h1);
    cudaGetSymbolAddress((void**)&W1h, g_W1h);
    cudaGetSymbolAddress((void**)&Wch, g_Wch);
    cudaGetSymbolAddress((void**)&W2h, g_W2h);
    cudaGetSymbolAddress((void**)&cnt2, g_cnt2);

    // dynamic smem: max(tile stages, C stage)
    const int smem128 = 128 * 128 * 4;     // 65536 (C stage dominates)
    const int smem64  = 128 * 64 * 4;      // 32768 (C stage dominates)

    static cudaStream_t s2 = nullptr;
    static cudaEvent_t evFork = nullptr, evJoin = nullptr;
    if (!s2) {
        cudaFuncSetAttribute(hgemm_kernel<128, 1, float, __half>,
                             cudaFuncAttributeMaxDynamicSharedMemorySize, smem128);
        cudaFuncSetAttribute(hgemm_kernel<128, 1, __half, __half>,
                             cudaFuncAttributeMaxDynamicSharedMemorySize, smem128);
        cudaFuncSetAttribute(hgemm_kernel<64, 2, __half, float>,
                             cudaFuncAttributeMaxDynamicSharedMemorySize, smem64);
        cudaStreamCreateWithFlags(&s2, cudaStreamNonBlocking);
        cudaEventCreateWithFlags(&evFork, cudaEventDisableTiming);
        cudaEventCreateWithFlags(&evJoin, cudaEventDisableTiming);
    }

    const int gemmGrid = M_TILES;                        // 782
    const int rowWarpGrid = (N_NODES * 32 + 255) / 256;  // warp per row
    const int edgeGrid = (N_EDGES + 255) / 256;
    const int rpGrid = (N_NODES + 1 + 255) / 256;        // 391
    const int wGrid = (IN_CH * HID + 255) / 256;

    // ---- fork: CSR build on s2, weights+GEMM1 on main (independent) ----
    cudaEventRecord(evFork, 0);
    cudaStreamWaitEvent(s2, evFork, 0);

    cudaMemsetAsync(cnt2, 0, 2 * N_NODES * sizeof(int), s2);
    probe_kernel<<<1, 32, 0, s2>>>((const int*)ei);
    count_kernel<<<edgeGrid, 256, 0, s2>>>(ei);
    part_dinv_kernel<<<SCAN_BLK, 256, 0, s2>>>();
    rowptr_scan_kernel<<<rpGrid, 256, 0, s2>>>();
    fill_kernel<<<edgeGrid, 256, 0, s2>>>(ei);
    cudaEventRecord(evJoin, s2);

    // weights -> fp16, then Stage 1: h0 = LN(GELU(x @ W1 + b1)) (fp16 out)
    convert_weights_kernel<<<wGrid, 256>>>(W1, Wc, W2);
    hgemm_kernel<128, 1, float, __half><<<gemmGrid, 256, smem128>>>(
        x, W1h, b1, g1, be1, h0, N_NODES, IN_CH);

    // ---- join: hops need both h0 and CSR ----
    cudaStreamWaitEvent(0, evJoin, 0);

    // Hop 1: h0 -> h1 ; Hop 2: h1 -> h0 (fp32 accumulate, fp16 store)
    spmm_hop_kernel<<<rowWarpGrid, 256>>>(h0, h1);
    spmm_hop_kernel<<<rowWarpGrid, 256>>>(h1, h0);

    // Stage 3: h1 = LN(GELU(h0 @ Wc + bc)); out = h1 @ W2 + b2
    hgemm_kernel<128, 1, __half, __half><<<gemmGrid, 256, smem128>>>(
        h0, Wch, bc, g2, be2, h1, N_NODES, HID);
    hgemm_kernel<64, 2, __half, float><<<gemmGrid, 256, smem64>>>(
        h1, W2h, b2, nullptr, nullptr, out, N_NODES, HID);
}